// round 12
// baseline (speedup 1.0000x reference)
#include <cuda_runtime.h>
#include <cstdint>

// ---------------- problem constants ----------------
#define B_      128
#define T_IN_   240
#define T_OUT_  30
#define D_      128
#define H_      256
#define G3_     768

#define ENC_LEN 30720   // T_IN * B
#define DEC_LEN 3840    // T_OUT * B

// segmentation: 3 chains per 4-CTA cluster
#define CHAINS   3
#define CHUNK    320     // 96 enc chains * 320 = 30720 ; 12 dec chains * 320 = 3840
#define WARMUP   96
#define STEPS    (CHUNK + WARMUP)   // 416
#define NCL_ENC  32
#define NCL_DEC  4

#define NTHREADS 384     // 12 warps

// ---------------- device scratch ----------------
__device__ float g_gi_enc[(size_t)ENC_LEN * G3_];   // ~94 MB
__device__ float g_gi_dec[(size_t)DEC_LEN * G3_];   // ~12 MB

// ---------------- helpers ----------------
__device__ __forceinline__ uint32_t smem_u32(const void* p) {
    return (uint32_t)__cvta_generic_to_shared(p);
}
__device__ __forceinline__ uint32_t mapa_u32(uint32_t addr, uint32_t rank) {
    uint32_t d;
    asm("mapa.shared::cluster.u32 %0, %1, %2;" : "=r"(d) : "r"(addr), "r"(rank));
    return d;
}
__device__ __forceinline__ void cl_sync() {
    asm volatile("barrier.cluster.arrive.aligned;" ::: "memory");
    asm volatile("barrier.cluster.wait.aligned;"   ::: "memory");
}
__device__ __forceinline__ void mbar_init(uint32_t mbar, uint32_t count) {
    asm volatile("mbarrier.init.shared.b64 [%0], %1;" :: "r"(mbar), "r"(count) : "memory");
}
__device__ __forceinline__ void mbar_arrive_expect(uint32_t mbar, uint32_t bytes) {
    asm volatile("mbarrier.arrive.expect_tx.shared::cta.b64 _, [%0], %1;"
                 :: "r"(mbar), "r"(bytes) : "memory");
}
__device__ __forceinline__ void mbar_wait_parity(uint32_t mbar, uint32_t parity) {
    uint32_t done;
    asm volatile(
        "{\n\t.reg .pred p;\n\t"
        "mbarrier.try_wait.parity.acquire.cta.shared::cta.b64 p, [%1], %2;\n\t"
        "selp.b32 %0, 1, 0, p;\n\t}"
        : "=r"(done) : "r"(mbar), "r"(parity) : "memory");
    if (!done) {
        asm volatile(
            "{\n\t.reg .pred P1;\n\t"
            "WAIT_LOOP_%=:\n\t"
            "mbarrier.try_wait.parity.acquire.cta.shared::cta.b64 P1, [%0], %1, 0x989680;\n\t"
            "@P1 bra.uni WAIT_DONE_%=;\n\t"
            "bra.uni WAIT_LOOP_%=;\n\t"
            "WAIT_DONE_%=:\n\t}"
            :: "r"(mbar), "r"(parity) : "memory");
    }
}
// bulk DSMEM copy: local shared -> peer CTA shared, tx-completing on peer mbar
__device__ __forceinline__ void bulk_dsmem(uint32_t dst, uint32_t src,
                                           uint32_t bytes, uint32_t mbar) {
    asm volatile(
        "cp.async.bulk.shared::cluster.shared::cta.mbarrier::complete_tx::bytes "
        "[%0], [%1], %2, [%3];"
        :: "r"(dst), "r"(src), "r"(bytes), "r"(mbar) : "memory");
}
__device__ __forceinline__ void fence_proxy_async_() {
    asm volatile("fence.proxy.async.shared::cta;" ::: "memory");
}
__device__ __forceinline__ void bar_sync_(int id, int cnt) {
    asm volatile("bar.sync %0, %1;" :: "r"(id), "r"(cnt) : "memory");
}
__device__ __forceinline__ unsigned long long ffma2(unsigned long long a,
                                                    unsigned long long b,
                                                    unsigned long long c) {
    unsigned long long r;
    asm("fma.rn.f32x2 %0, %1, %2, %3;" : "=l"(r) : "l"(a), "l"(b), "l"(c));
    return r;
}
__device__ __forceinline__ float f2lo(unsigned long long v) {
    return __uint_as_float((unsigned)(v & 0xffffffffull));
}
__device__ __forceinline__ float f2hi(unsigned long long v) {
    return __uint_as_float((unsigned)(v >> 32));
}
__device__ __forceinline__ float tanh_ap(float x) {
    float y;
    asm("tanh.approx.f32 %0, %1;" : "=f"(y) : "f"(x));
    return y;
}
__device__ __forceinline__ float sig_(float x) { return 0.5f * tanh_ap(0.5f * x) + 0.5f; }
__device__ __forceinline__ float th_(float x)  { return tanh_ap(x); }

// ============================================================
// Phase 1: GI = X @ Wih^T + bih  (unchanged — verified)
// ============================================================
__global__ __launch_bounds__(256)
void gi_gemm(const float* __restrict__ x,
             const float* __restrict__ Wih_e, const float* __restrict__ bih_e,
             const float* __restrict__ Wih_d, const float* __restrict__ bih_d)
{
    __shared__ float Xs[64][68];   // [k][pos]
    __shared__ float Ws[64][68];   // [k][gate]

    const int tileP = blockIdx.x;
    const bool enc = (tileP < (ENC_LEN / 64));
    const float* __restrict__ Wih = enc ? Wih_e : Wih_d;
    const float* __restrict__ bih = enc ? bih_e : bih_d;
    float* __restrict__ gout = enc ? g_gi_enc : g_gi_dec;
    const int p0 = (enc ? tileP : (tileP - ENC_LEN / 64)) * 64;
    const int g0 = blockIdx.y * 64;
    const int tid = threadIdx.x;
    const int tstride = enc ? 1 : 8;

    const int tx = tid & 15;
    const int ty = tid >> 4;
    float acc[4][4] = {};

    for (int kc = 0; kc < 2; ++kc) {
        #pragma unroll
        for (int i = tid; i < 64 * 64; i += 256) {
            int pos = i >> 6, k = i & 63;
            int p = p0 + pos;
            int b = p & 127, t = (p >> 7) * tstride;
            Xs[k][pos] = x[((size_t)b * T_IN_ + t) * D_ + kc * 64 + k];
        }
        #pragma unroll
        for (int i = tid; i < 64 * 64; i += 256) {
            int g = i >> 6, k = i & 63;
            Ws[k][g] = Wih[(size_t)(g0 + g) * D_ + kc * 64 + k];
        }
        __syncthreads();

        #pragma unroll 16
        for (int k = 0; k < 64; ++k) {
            float4 a = *(const float4*)&Xs[k][ty * 4];
            float4 b = *(const float4*)&Ws[k][tx * 4];
            float av[4] = {a.x, a.y, a.z, a.w};
            float bv[4] = {b.x, b.y, b.z, b.w};
            #pragma unroll
            for (int i = 0; i < 4; ++i)
                #pragma unroll
                for (int j = 0; j < 4; ++j)
                    acc[i][j] = fmaf(av[i], bv[j], acc[i][j]);
        }
        __syncthreads();
    }

    float bz[4];
    #pragma unroll
    for (int j = 0; j < 4; ++j) bz[j] = bih[g0 + tx * 4 + j];

    #pragma unroll
    for (int i = 0; i < 4; ++i) {
        int p = p0 + ty * 4 + i;
        float4 o;
        o.x = acc[i][0] + bz[0];
        o.y = acc[i][1] + bz[1];
        o.z = acc[i][2] + bz[2];
        o.w = acc[i][3] + bz[3];
        *(float4*)&gout[(size_t)p * G3_ + g0 + tx * 4] = o;
    }
}

// ============================================================
// Phase 2: segmented GRU scan — quarter-row mapping + BULK h-exchange.
// Exchange per step: gate threads STS h' into a local staging slice,
// gate warps bar.sync, then 12 threads issue cp.async.bulk (256B per
// chain per rank) completing tx on the peers' phase mbar.
// tx events per mbar per step: 12 (vs 768 scalar st.async) — tests
// the mbar tx-serialization theory. Wait/arm protocol identical R10.
// ============================================================
__global__ __launch_bounds__(NTHREADS, 1) __cluster_dims__(4, 1, 1)
void gru_scan(const float* __restrict__ Whh_e, const float* __restrict__ bhh_e,
              const float* __restrict__ Whh_d, const float* __restrict__ bhh_d,
              float* __restrict__ out)
{
    __shared__ __align__(16) float hbuf[2][CHAINS][256];   // [parity][chain][H]
    __shared__ __align__(16) float hstage[2][CHAINS][64];  // local h' staging
    __shared__ float sGHp[CHAINS][4][192];                 // [chain][quarter][row]
    __shared__ float sGI[CHAINS][192];
    __shared__ float sBH[192];
    __shared__ __align__(8) unsigned long long mbars[2];   // one per parity

    const int tid  = threadIdx.x;
    const int warp = tid >> 5;
    const int lane = tid & 31;
    uint32_t rank;
    asm("mov.u32 %0, %%cluster_ctarank;" : "=r"(rank));

    const int cl   = blockIdx.x >> 2;
    const bool enc = cl < NCL_ENC;
    const int lcl  = enc ? cl : cl - NCL_ENC;
    const float* __restrict__ Whh = enc ? Whh_e : Whh_d;
    const float* __restrict__ bhh = enc ? bhh_e : bhh_d;
    const float* __restrict__ gi  = enc ? g_gi_enc : g_gi_dec;

    int base[CHAINS];
    #pragma unroll
    for (int c = 0; c < CHAINS; ++c)
        base[c] = (lcl * CHAINS + c) * CHUNK;

    const uint32_t mb_base = smem_u32(&mbars[0]);

    // ---- shared init ----
    for (int i = tid; i < 2 * CHAINS * 256; i += NTHREADS)
        ((float*)hbuf)[i] = 0.0f;
    if (tid < 192) {
        int g = tid >> 6, j = tid & 63;
        sBH[tid] = bhh[g * 256 + (int)rank * 64 + j];
    }
    if (tid == 0) {
        mbar_init(mb_base, 1);
        mbar_init(mb_base + 8, 1);
        // pre-arm mb[1]: it receives step-0 copies (3 chains x 4 ranks x 256B)
        mbar_arrive_expect(mb_base + 8, 1024 * CHAINS);
    }
    __syncthreads();
    cl_sync();   // barriers + zeroed buffers visible cluster-wide

    // ---- thread mapping: 2 rows x one k-quarter ----
    const int q  = warp & 3;            // k-quarter 0..3
    const int g  = warp >> 2;           // row-group 0..2
    const int r0 = g * 32 + lane;       // 0..95
    const int r1 = r0 + 96;             // 96..191
    const int Rg0 = (r0 >> 6) * 256 + (int)rank * 64 + (r0 & 63);
    const int Rg1 = (r1 >> 6) * 256 + (int)rank * 64 + (r1 & 63);

    // 2 x 64 weights in registers (64 packed f32x2 total)
    unsigned long long wA[32], wB[32];
    {
        const ulonglong2* w0 = (const ulonglong2*)(Whh + (size_t)Rg0 * H_ + q * 64);
        const ulonglong2* w1 = (const ulonglong2*)(Whh + (size_t)Rg1 * H_ + q * 64);
        #pragma unroll
        for (int i = 0; i < 16; ++i) {
            ulonglong2 t0 = w0[i];
            wA[2 * i] = t0.x; wA[2 * i + 1] = t0.y;
            ulonglong2 t1 = w1[i];
            wB[2 * i] = t1.x; wB[2 * i + 1] = t1.y;
        }
    }

    // peer addresses
    uint32_t peer_hb[4], peer_mb[4];
    {
        uint32_t my_hb = smem_u32(&hbuf[0][0][0]);
        #pragma unroll
        for (int r = 0; r < 4; ++r) {
            peer_hb[r] = mapa_u32(my_hb, r);
            peer_mb[r] = mapa_u32(mb_base, r);
        }
    }

    // per-chain gi pointers; q==0 threads prefetch both rows one step ahead
    const float* gp[CHAINS];
    float gin0[CHAINS], gin1[CHAINS];
    #pragma unroll
    for (int c = 0; c < CHAINS; ++c) {
        int p0 = base[c] - WARMUP; if (p0 < 0) p0 = 0;
        gp[c] = gi + (size_t)p0 * G3_;
        if (q == 0) {
            gin0[c] = __ldg(gp[c] + Rg0);
            gin1[c] = __ldg(gp[c] + Rg1);
        } else { gin0[c] = 0.0f; gin1[c] = 0.0f; }
    }

    uint32_t mph[2] = {0u, 0u};

    for (int s = 0; s < STEPS; ++s) {
        const int ph = s & 1;

        // wait for all chains' h(s) (bulk-copied at end of step s-1)
        if (s > 0) {
            mbar_wait_parity(mb_base + ph * 8, mph[ph] & 1u);
            mph[ph]++;
        }

        // arm mb[ph] for step (s+1)'s copies — AFTER the wait (unique
        // arrive of the fresh phase; R10's proven ordering).
        if (tid == 0 && s + 1 < STEPS)
            mbar_arrive_expect(mb_base + ph * 8, 1024 * CHAINS);

        // ---- 3 matvecs back-to-back ----
        #pragma unroll
        for (int c = 0; c < CHAINS; ++c) {
            float giv0 = gin0[c], giv1 = gin1[c];
            if (q == 0 && s + 1 < STEPS) {         // guarded prefetch
                if (base[c] + s + 1 > WARMUP) gp[c] += G3_;
                gin0[c] = __ldg(gp[c] + Rg0);
                gin1[c] = __ldg(gp[c] + Rg1);
            }

            const ulonglong2* h2 =
                (const ulonglong2*)(&hbuf[ph][c][0]) + q * 16;
            unsigned long long a = 0ull, b = 0ull;
            #pragma unroll
            for (int i = 0; i < 16; ++i) {
                ulonglong2 hv = h2[i];            // 1 LDS.128 -> 4 FFMA2
                a = ffma2(wA[2 * i],     hv.x, a);
                a = ffma2(wA[2 * i + 1], hv.y, a);
                b = ffma2(wB[2 * i],     hv.x, b);
                b = ffma2(wB[2 * i + 1], hv.y, b);
            }
            sGHp[c][q][r0] = f2lo(a) + f2hi(a);
            sGHp[c][q][r1] = f2lo(b) + f2hi(b);
            if (q == 0) {
                sGI[c][r0] = giv0;
                sGI[c][r1] = giv1;
            }
        }
        __syncthreads();   // all partials visible; arm ordered before copies

        // ---- gates: 192 threads = 3 chains x 64 coords ----
        if (tid < 64 * CHAINS) {
            const int c = tid >> 6;
            const int j = tid & 63;
            const int p = base[c] + s - WARMUP;

            float ghr = sGHp[c][0][j]       + sGHp[c][1][j]
                      + sGHp[c][2][j]       + sGHp[c][3][j]       + sBH[j];
            float ghz = sGHp[c][0][64 + j]  + sGHp[c][1][64 + j]
                      + sGHp[c][2][64 + j]  + sGHp[c][3][64 + j]  + sBH[64 + j];
            float ghn = sGHp[c][0][128 + j] + sGHp[c][1][128 + j]
                      + sGHp[c][2][128 + j] + sGHp[c][3][128 + j] + sBH[128 + j];
            float r_ = sig_(sGI[c][j]       + ghr);
            float z_ = sig_(sGI[c][64 + j]  + ghz);
            float n_ = th_ (sGI[c][128 + j] + r_ * ghn);
            float hold = hbuf[ph][c][(int)rank * 64 + j];
            float hn = (1.0f - z_) * n_ + z_ * hold;
            if (p < 0) hn = 0.0f;   // pre-sequence region of segment 0

            hstage[ph][c][j] = hn;   // local staging for bulk copy

            if (s >= WARMUP) {
                if (enc) {
                    if ((p & 127) == 127) {
                        int t_out = p >> 7;
                        out[(size_t)t_out * H_ + rank * 64 + j] = hn;
                    }
                } else {
                    int b = p & 127, t = p >> 7;
                    out[(size_t)(T_IN_ * H_) +
                        ((size_t)b * T_OUT_ + t) * H_ + rank * 64 + j] = hn;
                }
            }
        }

        // ---- bulk h-exchange: 12 copies of 256B (chain c -> rank r) ----
        if (s + 1 < STEPS) {
            if (tid < 192) bar_sync_(2, 192);   // gate STS visible
            if (tid < 12) {
                fence_proxy_async_();           // order STS into async proxy
                const int c = tid >> 2;
                const int r = tid & 3;
                uint32_t dst = peer_hb[r]
                    + (uint32_t)((((ph ^ 1) * CHAINS + c) << 10) + (int)rank * 256);
                uint32_t src = smem_u32(&hstage[ph][c][0]);
                bulk_dsmem(dst, src, 256u, peer_mb[r] + (uint32_t)(ph ^ 1) * 8u);
            }
        }
        // staging WAR: hstage[ph] is rewritten at step s+2, by which time
        // this step's bulks have fully completed (they fed the mbar phase
        // every CTA waited on at step s+1).
    }

    cl_sync();   // drain async traffic before cluster teardown
}

// ============================================================
// launch
// ============================================================
extern "C" void kernel_launch(void* const* d_in, const int* in_sizes, int n_in,
                              void* d_out, int out_size)
{
    const float* x     = (const float*)d_in[0];
    const float* Wih_e = (const float*)d_in[1];
    const float* Whh_e = (const float*)d_in[2];
    const float* bih_e = (const float*)d_in[3];
    const float* bhh_e = (const float*)d_in[4];
    const float* Wih_d = (const float*)d_in[5];
    const float* Whh_d = (const float*)d_in[6];
    const float* bih_d = (const float*)d_in[7];
    const float* bhh_d = (const float*)d_in[8];
    float* out = (float*)d_out;

    dim3 ggrid(ENC_LEN / 64 + DEC_LEN / 64, G3_ / 64);  // (540, 12)
    gi_gemm<<<ggrid, 256>>>(x, Wih_e, bih_e, Wih_d, bih_d);

    gru_scan<<<(NCL_ENC + NCL_DEC) * 4, NTHREADS>>>(
        Whh_e, bhh_e, Whh_d, bhh_d, out);
}

// round 13
// speedup vs baseline: 1.4083x; 1.4083x over previous
#include <cuda_runtime.h>
#include <cstdint>

// ---------------- problem constants ----------------
#define B_      128
#define T_IN_   240
#define T_OUT_  30
#define D_      128
#define H_      256
#define G3_     768

#define ENC_LEN 30720   // T_IN * B
#define DEC_LEN 3840    // T_OUT * B

// segmentation: 6 chains per 4-CTA cluster
#define CHAINS   6
#define CHUNK    160     // 192 enc chains * 160 = 30720 ; 24 dec chains * 160 = 3840
#define WARMUP   96
#define STEPS    (CHUNK + WARMUP)   // 256
#define NCL_ENC  32
#define NCL_DEC  4

#define NTHREADS 384     // 12 warps; every thread is one gate (c,j)

// ---------------- device scratch ----------------
__device__ float g_gi_enc[(size_t)ENC_LEN * G3_];   // ~94 MB
__device__ float g_gi_dec[(size_t)DEC_LEN * G3_];   // ~12 MB

// ---------------- helpers ----------------
__device__ __forceinline__ uint32_t smem_u32(const void* p) {
    return (uint32_t)__cvta_generic_to_shared(p);
}
__device__ __forceinline__ uint32_t mapa_u32(uint32_t addr, uint32_t rank) {
    uint32_t d;
    asm("mapa.shared::cluster.u32 %0, %1, %2;" : "=r"(d) : "r"(addr), "r"(rank));
    return d;
}
__device__ __forceinline__ void cl_sync() {
    asm volatile("barrier.cluster.arrive.aligned;" ::: "memory");
    asm volatile("barrier.cluster.wait.aligned;"   ::: "memory");
}
__device__ __forceinline__ void mbar_init(uint32_t mbar, uint32_t count) {
    asm volatile("mbarrier.init.shared.b64 [%0], %1;" :: "r"(mbar), "r"(count) : "memory");
}
__device__ __forceinline__ void mbar_arrive_expect(uint32_t mbar, uint32_t bytes) {
    asm volatile("mbarrier.arrive.expect_tx.shared::cta.b64 _, [%0], %1;"
                 :: "r"(mbar), "r"(bytes) : "memory");
}
__device__ __forceinline__ void mbar_wait_parity(uint32_t mbar, uint32_t parity) {
    uint32_t done;
    asm volatile(
        "{\n\t.reg .pred p;\n\t"
        "mbarrier.try_wait.parity.acquire.cta.shared::cta.b64 p, [%1], %2;\n\t"
        "selp.b32 %0, 1, 0, p;\n\t}"
        : "=r"(done) : "r"(mbar), "r"(parity) : "memory");
    if (!done) {
        asm volatile(
            "{\n\t.reg .pred P1;\n\t"
            "WAIT_LOOP_%=:\n\t"
            "mbarrier.try_wait.parity.acquire.cta.shared::cta.b64 P1, [%0], %1, 0x989680;\n\t"
            "@P1 bra.uni WAIT_DONE_%=;\n\t"
            "bra.uni WAIT_LOOP_%=;\n\t"
            "WAIT_DONE_%=:\n\t}"
            :: "r"(mbar), "r"(parity) : "memory");
    }
}
__device__ __forceinline__ void st_async_f32(uint32_t addr, float v, uint32_t mbar) {
    asm volatile(
        "st.async.weak.shared::cluster.mbarrier::complete_tx::bytes.f32 [%0], %1, [%2];"
        :: "r"(addr), "f"(v), "r"(mbar) : "memory");
}
__device__ __forceinline__ unsigned long long ffma2(unsigned long long a,
                                                    unsigned long long b,
                                                    unsigned long long c) {
    unsigned long long r;
    asm("fma.rn.f32x2 %0, %1, %2, %3;" : "=l"(r) : "l"(a), "l"(b), "l"(c));
    return r;
}
__device__ __forceinline__ float f2lo(unsigned long long v) {
    return __uint_as_float((unsigned)(v & 0xffffffffull));
}
__device__ __forceinline__ float f2hi(unsigned long long v) {
    return __uint_as_float((unsigned)(v >> 32));
}
__device__ __forceinline__ float tanh_ap(float x) {
    float y;
    asm("tanh.approx.f32 %0, %1;" : "=f"(y) : "f"(x));
    return y;
}
__device__ __forceinline__ float sig_(float x) { return 0.5f * tanh_ap(0.5f * x) + 0.5f; }
__device__ __forceinline__ float th_(float x)  { return tanh_ap(x); }

// ============================================================
// Phase 1: GI = X @ Wih^T + bih  (unchanged — verified)
// ============================================================
__global__ __launch_bounds__(256)
void gi_gemm(const float* __restrict__ x,
             const float* __restrict__ Wih_e, const float* __restrict__ bih_e,
             const float* __restrict__ Wih_d, const float* __restrict__ bih_d)
{
    __shared__ float Xs[64][68];   // [k][pos]
    __shared__ float Ws[64][68];   // [k][gate]

    const int tileP = blockIdx.x;
    const bool enc = (tileP < (ENC_LEN / 64));
    const float* __restrict__ Wih = enc ? Wih_e : Wih_d;
    const float* __restrict__ bih = enc ? bih_e : bih_d;
    float* __restrict__ gout = enc ? g_gi_enc : g_gi_dec;
    const int p0 = (enc ? tileP : (tileP - ENC_LEN / 64)) * 64;
    const int g0 = blockIdx.y * 64;
    const int tid = threadIdx.x;
    const int tstride = enc ? 1 : 8;

    const int tx = tid & 15;
    const int ty = tid >> 4;
    float acc[4][4] = {};

    for (int kc = 0; kc < 2; ++kc) {
        #pragma unroll
        for (int i = tid; i < 64 * 64; i += 256) {
            int pos = i >> 6, k = i & 63;
            int p = p0 + pos;
            int b = p & 127, t = (p >> 7) * tstride;
            Xs[k][pos] = x[((size_t)b * T_IN_ + t) * D_ + kc * 64 + k];
        }
        #pragma unroll
        for (int i = tid; i < 64 * 64; i += 256) {
            int g = i >> 6, k = i & 63;
            Ws[k][g] = Wih[(size_t)(g0 + g) * D_ + kc * 64 + k];
        }
        __syncthreads();

        #pragma unroll 16
        for (int k = 0; k < 64; ++k) {
            float4 a = *(const float4*)&Xs[k][ty * 4];
            float4 b = *(const float4*)&Ws[k][tx * 4];
            float av[4] = {a.x, a.y, a.z, a.w};
            float bv[4] = {b.x, b.y, b.z, b.w};
            #pragma unroll
            for (int i = 0; i < 4; ++i)
                #pragma unroll
                for (int j = 0; j < 4; ++j)
                    acc[i][j] = fmaf(av[i], bv[j], acc[i][j]);
        }
        __syncthreads();
    }

    float bz[4];
    #pragma unroll
    for (int j = 0; j < 4; ++j) bz[j] = bih[g0 + tx * 4 + j];

    #pragma unroll
    for (int i = 0; i < 4; ++i) {
        int p = p0 + ty * 4 + i;
        float4 o;
        o.x = acc[i][0] + bz[0];
        o.y = acc[i][1] + bz[1];
        o.z = acc[i][2] + bz[2];
        o.w = acc[i][3] + bz[3];
        *(float4*)&gout[(size_t)p * G3_ + g0 + tx * 4] = o;
    }
}

// ============================================================
// Phase 2: segmented GRU scan — 6 chains per step, ONE exchange.
// Matvec: quarter-row mapping (warp q=w&3, rows g*32+lane, +96),
//   broadcast LDS, 1 LDS.128 -> 4 FFMA2, 6 chains back-to-back.
// Gates: ALL 384 threads, one (c,j) pair each (c=tid>>6, j=tid&63);
//   each thread LDGs its own 3 gi values at step top (before the
//   mbar wait -> latency hidden). Scalar st.async exchange (R10/R11
//   proven), wait-then-arm protocol identical.
// ============================================================
__global__ __launch_bounds__(NTHREADS, 1) __cluster_dims__(4, 1, 1)
void gru_scan(const float* __restrict__ Whh_e, const float* __restrict__ bhh_e,
              const float* __restrict__ Whh_d, const float* __restrict__ bhh_d,
              float* __restrict__ out)
{
    __shared__ __align__(16) float hbuf[2][CHAINS][256];   // [parity][chain][H]
    __shared__ float sGHp[CHAINS][4][192];                 // [chain][quarter][row]
    __shared__ float sBH[192];
    __shared__ __align__(8) unsigned long long mbars[2];   // one per parity

    const int tid  = threadIdx.x;
    const int warp = tid >> 5;
    const int lane = tid & 31;
    uint32_t rank;
    asm("mov.u32 %0, %%cluster_ctarank;" : "=r"(rank));

    const int cl   = blockIdx.x >> 2;
    const bool enc = cl < NCL_ENC;
    const int lcl  = enc ? cl : cl - NCL_ENC;
    const float* __restrict__ Whh = enc ? Whh_e : Whh_d;
    const float* __restrict__ bhh = enc ? bhh_e : bhh_d;
    const float* __restrict__ gi  = enc ? g_gi_enc : g_gi_dec;

    const uint32_t mb_base = smem_u32(&mbars[0]);

    // ---- shared init ----
    for (int i = tid; i < 2 * CHAINS * 256; i += NTHREADS)
        ((float*)hbuf)[i] = 0.0f;
    if (tid < 192) {
        int g = tid >> 6, j = tid & 63;
        sBH[tid] = bhh[g * 256 + (int)rank * 64 + j];
    }
    if (tid == 0) {
        mbar_init(mb_base, 1);
        mbar_init(mb_base + 8, 1);
        // pre-arm mb[1]: receives step-0 stores (6 chains x 256 coords x 4B)
        mbar_arrive_expect(mb_base + 8, 1024 * CHAINS);
    }
    __syncthreads();
    cl_sync();   // barriers + zeroed buffers visible cluster-wide

    // ---- matvec mapping: 2 rows x one k-quarter ----
    const int q  = warp & 3;            // k-quarter 0..3
    const int g  = warp >> 2;           // row-group 0..2
    const int r0 = g * 32 + lane;       // 0..95
    const int r1 = r0 + 96;             // 96..191
    const int Rg0 = (r0 >> 6) * 256 + (int)rank * 64 + (r0 & 63);
    const int Rg1 = (r1 >> 6) * 256 + (int)rank * 64 + (r1 & 63);

    // 2 x 64 weights in registers (64 packed f32x2 total)
    unsigned long long wA[32], wB[32];
    {
        const ulonglong2* w0 = (const ulonglong2*)(Whh + (size_t)Rg0 * H_ + q * 64);
        const ulonglong2* w1 = (const ulonglong2*)(Whh + (size_t)Rg1 * H_ + q * 64);
        #pragma unroll
        for (int i = 0; i < 16; ++i) {
            ulonglong2 t0 = w0[i];
            wA[2 * i] = t0.x; wA[2 * i + 1] = t0.y;
            ulonglong2 t1 = w1[i];
            wB[2 * i] = t1.x; wB[2 * i + 1] = t1.y;
        }
    }

    // ---- gate mapping: one (chain, coord) per thread ----
    const int gc = tid >> 6;            // chain 0..5
    const int gj = tid & 63;            // coord 0..63
    const int gbase = (lcl * CHAINS + gc) * CHUNK;
    const int goff  = (int)rank * 64 + gj;  // within-row offset (gate-major rows)
    // gi row pointer for this thread's chain (clamped start)
    const float* gpt;
    {
        int p0 = gbase - WARMUP; if (p0 < 0) p0 = 0;
        gpt = gi + (size_t)p0 * G3_ + goff;
    }

    // peer addresses
    uint32_t peer_hb[4], peer_mb[4];
    {
        uint32_t my_hb = smem_u32(&hbuf[0][0][0]);
        #pragma unroll
        for (int r = 0; r < 4; ++r) {
            peer_hb[r] = mapa_u32(my_hb, r);
            peer_mb[r] = mapa_u32(mb_base, r);
        }
    }

    uint32_t mph[2] = {0u, 0u};

    for (int s = 0; s < STEPS; ++s) {
        const int ph = s & 1;

        // ---- gi loads for THIS step (issued before the wait: hidden) ----
        float gv0 = __ldg(gpt);
        float gv1 = __ldg(gpt + 256);
        float gv2 = __ldg(gpt + 512);
        if (gbase + s + 1 > WARMUP) gpt += G3_;   // clamp only chain 0 warmup

        // wait for all chains' h(s) (stored at end of step s-1)
        if (s > 0) {
            mbar_wait_parity(mb_base + ph * 8, mph[ph] & 1u);
            mph[ph]++;
        }

        // arm mb[ph] for step (s+1)'s stores — AFTER the wait (unique
        // arrive of the fresh phase; proven ordering).
        if (tid == 0 && s + 1 < STEPS)
            mbar_arrive_expect(mb_base + ph * 8, 1024 * CHAINS);

        // ---- 6 matvecs back-to-back ----
        #pragma unroll
        for (int c = 0; c < CHAINS; ++c) {
            const ulonglong2* h2 =
                (const ulonglong2*)(&hbuf[ph][c][0]) + q * 16;
            unsigned long long a = 0ull, b = 0ull;
            #pragma unroll
            for (int i = 0; i < 16; ++i) {
                ulonglong2 hv = h2[i];            // 1 LDS.128 -> 4 FFMA2
                a = ffma2(wA[2 * i],     hv.x, a);
                a = ffma2(wA[2 * i + 1], hv.y, a);
                b = ffma2(wB[2 * i],     hv.x, b);
                b = ffma2(wB[2 * i + 1], hv.y, b);
            }
            sGHp[c][q][r0] = f2lo(a) + f2hi(a);
            sGHp[c][q][r1] = f2lo(b) + f2hi(b);
        }
        __syncthreads();   // all partials visible; arm ordered before stores

        // ---- gates: ALL 384 threads, one (c,j) each ----
        {
            const int p = gbase + s - WARMUP;

            float ghr = sGHp[gc][0][gj]       + sGHp[gc][1][gj]
                      + sGHp[gc][2][gj]       + sGHp[gc][3][gj]       + sBH[gj];
            float ghz = sGHp[gc][0][64 + gj]  + sGHp[gc][1][64 + gj]
                      + sGHp[gc][2][64 + gj]  + sGHp[gc][3][64 + gj]  + sBH[64 + gj];
            float ghn = sGHp[gc][0][128 + gj] + sGHp[gc][1][128 + gj]
                      + sGHp[gc][2][128 + gj] + sGHp[gc][3][128 + gj] + sBH[128 + gj];
            float r_ = sig_(gv0 + ghr);
            float z_ = sig_(gv1 + ghz);
            float n_ = th_ (gv2 + r_ * ghn);
            float hold = hbuf[ph][gc][goff];
            float hn = (1.0f - z_) * n_ + z_ * hold;
            if (p < 0) hn = 0.0f;   // pre-sequence region of chain 0

            if (s + 1 < STEPS) {
                uint32_t boff = (uint32_t)(((ph ^ 1) * CHAINS + gc) * 256 + goff) * 4u;
                uint32_t moff = (uint32_t)(ph ^ 1) * 8u;
                #pragma unroll
                for (int r = 0; r < 4; ++r)
                    st_async_f32(peer_hb[r] + boff, hn, peer_mb[r] + moff);
            }

            if (s >= WARMUP) {
                if (enc) {
                    if ((p & 127) == 127) {
                        int t_out = p >> 7;
                        out[(size_t)t_out * H_ + goff] = hn;
                    }
                } else {
                    int b = p & 127, t = p >> 7;
                    out[(size_t)(T_IN_ * H_) +
                        ((size_t)b * T_OUT_ + t) * H_ + goff] = hn;
                }
            }
        }
        // no trailing barrier: next step's mbar wait provides data ordering
        // (h arrivals) and WAR protection (any thread passing the wait
        // implies all local threads issued their stores, hence finished
        // their sGHp reads).
    }

    cl_sync();   // drain async traffic before cluster teardown
}

// ============================================================
// launch
// ============================================================
extern "C" void kernel_launch(void* const* d_in, const int* in_sizes, int n_in,
                              void* d_out, int out_size)
{
    const float* x     = (const float*)d_in[0];
    const float* Wih_e = (const float*)d_in[1];
    const float* Whh_e = (const float*)d_in[2];
    const float* bih_e = (const float*)d_in[3];
    const float* bhh_e = (const float*)d_in[4];
    const float* Wih_d = (const float*)d_in[5];
    const float* Whh_d = (const float*)d_in[6];
    const float* bih_d = (const float*)d_in[7];
    const float* bhh_d = (const float*)d_in[8];
    float* out = (float*)d_out;

    dim3 ggrid(ENC_LEN / 64 + DEC_LEN / 64, G3_ / 64);  // (540, 12)
    gi_gemm<<<ggrid, 256>>>(x, Wih_e, bih_e, Wih_d, bih_d);

    gru_scan<<<(NCL_ENC + NCL_DEC) * 4, NTHREADS>>>(
        Whh_e, bhh_e, Whh_d, bhh_d, out);
}

// round 14
// speedup vs baseline: 1.4411x; 1.0233x over previous
#include <cuda_runtime.h>
#include <cstdint>

// ---------------- problem constants ----------------
#define B_      128
#define T_IN_   240
#define T_OUT_  30
#define D_      128
#define H_      256
#define G3_     768

#define ENC_LEN 30720   // T_IN * B
#define DEC_LEN 3840    // T_OUT * B

// segmentation: 6 chains per 4-CTA cluster, 2 pipelined groups of 3
#define CHAINS   6
#define GCH      3       // chains per group
#define CHUNK    160     // 192 enc chains * 160 = 30720 ; 24 dec chains * 160 = 3840
#define WARMUP   96
#define STEPS    (CHUNK + WARMUP)   // 256
#define NCL_ENC  32
#define NCL_DEC  4

#define NTHREADS 384     // 12 warps; every thread is one gate (c,j)

// ---------------- device scratch ----------------
__device__ float g_gi_enc[(size_t)ENC_LEN * G3_];   // ~94 MB
__device__ float g_gi_dec[(size_t)DEC_LEN * G3_];   // ~12 MB

// ---------------- helpers ----------------
__device__ __forceinline__ uint32_t smem_u32(const void* p) {
    return (uint32_t)__cvta_generic_to_shared(p);
}
__device__ __forceinline__ uint32_t mapa_u32(uint32_t addr, uint32_t rank) {
    uint32_t d;
    asm("mapa.shared::cluster.u32 %0, %1, %2;" : "=r"(d) : "r"(addr), "r"(rank));
    return d;
}
__device__ __forceinline__ void cl_sync() {
    asm volatile("barrier.cluster.arrive.aligned;" ::: "memory");
    asm volatile("barrier.cluster.wait.aligned;"   ::: "memory");
}
__device__ __forceinline__ void mbar_init(uint32_t mbar, uint32_t count) {
    asm volatile("mbarrier.init.shared.b64 [%0], %1;" :: "r"(mbar), "r"(count) : "memory");
}
__device__ __forceinline__ void mbar_arrive_expect(uint32_t mbar, uint32_t bytes) {
    asm volatile("mbarrier.arrive.expect_tx.shared::cta.b64 _, [%0], %1;"
                 :: "r"(mbar), "r"(bytes) : "memory");
}
__device__ __forceinline__ void mbar_wait_parity(uint32_t mbar, uint32_t parity) {
    uint32_t done;
    asm volatile(
        "{\n\t.reg .pred p;\n\t"
        "mbarrier.try_wait.parity.acquire.cta.shared::cta.b64 p, [%1], %2;\n\t"
        "selp.b32 %0, 1, 0, p;\n\t}"
        : "=r"(done) : "r"(mbar), "r"(parity) : "memory");
    if (!done) {
        asm volatile(
            "{\n\t.reg .pred P1;\n\t"
            "WAIT_LOOP_%=:\n\t"
            "mbarrier.try_wait.parity.acquire.cta.shared::cta.b64 P1, [%0], %1, 0x989680;\n\t"
            "@P1 bra.uni WAIT_DONE_%=;\n\t"
            "bra.uni WAIT_LOOP_%=;\n\t"
            "WAIT_DONE_%=:\n\t}"
            :: "r"(mbar), "r"(parity) : "memory");
    }
}
__device__ __forceinline__ void st_async_f32(uint32_t addr, float v, uint32_t mbar) {
    asm volatile(
        "st.async.weak.shared::cluster.mbarrier::complete_tx::bytes.f32 [%0], %1, [%2];"
        :: "r"(addr), "f"(v), "r"(mbar) : "memory");
}
__device__ __forceinline__ unsigned long long ffma2(unsigned long long a,
                                                    unsigned long long b,
                                                    unsigned long long c) {
    unsigned long long r;
    asm("fma.rn.f32x2 %0, %1, %2, %3;" : "=l"(r) : "l"(a), "l"(b), "l"(c));
    return r;
}
__device__ __forceinline__ float f2lo(unsigned long long v) {
    return __uint_as_float((unsigned)(v & 0xffffffffull));
}
__device__ __forceinline__ float f2hi(unsigned long long v) {
    return __uint_as_float((unsigned)(v >> 32));
}
__device__ __forceinline__ float tanh_ap(float x) {
    float y;
    asm("tanh.approx.f32 %0, %1;" : "=f"(y) : "f"(x));
    return y;
}
__device__ __forceinline__ float sig_(float x) { return 0.5f * tanh_ap(0.5f * x) + 0.5f; }
__device__ __forceinline__ float th_(float x)  { return tanh_ap(x); }

// ============================================================
// Phase 1: GI = X @ Wih^T + bih  (unchanged — verified)
// ============================================================
__global__ __launch_bounds__(256)
void gi_gemm(const float* __restrict__ x,
             const float* __restrict__ Wih_e, const float* __restrict__ bih_e,
             const float* __restrict__ Wih_d, const float* __restrict__ bih_d)
{
    __shared__ float Xs[64][68];   // [k][pos]
    __shared__ float Ws[64][68];   // [k][gate]

    const int tileP = blockIdx.x;
    const bool enc = (tileP < (ENC_LEN / 64));
    const float* __restrict__ Wih = enc ? Wih_e : Wih_d;
    const float* __restrict__ bih = enc ? bih_e : bih_d;
    float* __restrict__ gout = enc ? g_gi_enc : g_gi_dec;
    const int p0 = (enc ? tileP : (tileP - ENC_LEN / 64)) * 64;
    const int g0 = blockIdx.y * 64;
    const int tid = threadIdx.x;
    const int tstride = enc ? 1 : 8;

    const int tx = tid & 15;
    const int ty = tid >> 4;
    float acc[4][4] = {};

    for (int kc = 0; kc < 2; ++kc) {
        #pragma unroll
        for (int i = tid; i < 64 * 64; i += 256) {
            int pos = i >> 6, k = i & 63;
            int p = p0 + pos;
            int b = p & 127, t = (p >> 7) * tstride;
            Xs[k][pos] = x[((size_t)b * T_IN_ + t) * D_ + kc * 64 + k];
        }
        #pragma unroll
        for (int i = tid; i < 64 * 64; i += 256) {
            int g = i >> 6, k = i & 63;
            Ws[k][g] = Wih[(size_t)(g0 + g) * D_ + kc * 64 + k];
        }
        __syncthreads();

        #pragma unroll 16
        for (int k = 0; k < 64; ++k) {
            float4 a = *(const float4*)&Xs[k][ty * 4];
            float4 b = *(const float4*)&Ws[k][tx * 4];
            float av[4] = {a.x, a.y, a.z, a.w};
            float bv[4] = {b.x, b.y, b.z, b.w};
            #pragma unroll
            for (int i = 0; i < 4; ++i)
                #pragma unroll
                for (int j = 0; j < 4; ++j)
                    acc[i][j] = fmaf(av[i], bv[j], acc[i][j]);
        }
        __syncthreads();
    }

    float bz[4];
    #pragma unroll
    for (int j = 0; j < 4; ++j) bz[j] = bih[g0 + tx * 4 + j];

    #pragma unroll
    for (int i = 0; i < 4; ++i) {
        int p = p0 + ty * 4 + i;
        float4 o;
        o.x = acc[i][0] + bz[0];
        o.y = acc[i][1] + bz[1];
        o.z = acc[i][2] + bz[2];
        o.w = acc[i][3] + bz[3];
        *(float4*)&gout[(size_t)p * G3_ + g0 + tx * 4] = o;
    }
}

// ============================================================
// Phase 2: segmented GRU scan — 6 chains in 2 pipelined groups.
// Group g (chains 3g..3g+2) has its own mbar pair; per step:
//   waitA -> armA -> matvec A -> sync -> gatesA+storesA ->
//   waitB -> armB -> matvec B -> sync -> gatesB+storesB
// Each group's exchange latency hides under the OTHER group's
// matvec. Per-group barrier protocol == R10 proven (wait-then-arm,
// arm before that group's stores via its own syncthreads).
// ============================================================
__global__ __launch_bounds__(NTHREADS, 1) __cluster_dims__(4, 1, 1)
void gru_scan(const float* __restrict__ Whh_e, const float* __restrict__ bhh_e,
              const float* __restrict__ Whh_d, const float* __restrict__ bhh_d,
              float* __restrict__ out)
{
    __shared__ __align__(16) float hbuf[2][CHAINS][256];   // [parity][chain][H]
    __shared__ float sGHp[CHAINS][4][192];                 // [chain][quarter][row]
    __shared__ float sBH[192];
    __shared__ __align__(8) unsigned long long mbars[2][2]; // [group][parity]

    const int tid  = threadIdx.x;
    const int warp = tid >> 5;
    const int lane = tid & 31;
    uint32_t rank;
    asm("mov.u32 %0, %%cluster_ctarank;" : "=r"(rank));

    const int cl   = blockIdx.x >> 2;
    const bool enc = cl < NCL_ENC;
    const int lcl  = enc ? cl : cl - NCL_ENC;
    const float* __restrict__ Whh = enc ? Whh_e : Whh_d;
    const float* __restrict__ bhh = enc ? bhh_e : bhh_d;
    const float* __restrict__ gi  = enc ? g_gi_enc : g_gi_dec;

    const uint32_t mb_base = smem_u32(&mbars[0][0]);
    // mbar addr: mb_base + (group*2 + parity)*8

    // ---- shared init ----
    for (int i = tid; i < 2 * CHAINS * 256; i += NTHREADS)
        ((float*)hbuf)[i] = 0.0f;
    if (tid < 192) {
        int g = tid >> 6, j = tid & 63;
        sBH[tid] = bhh[g * 256 + (int)rank * 64 + j];
    }
    if (tid == 0) {
        #pragma unroll
        for (int i = 0; i < 4; ++i) mbar_init(mb_base + i * 8, 1);
        // pre-arm parity-1 barriers of both groups (step-0 stores land there)
        mbar_arrive_expect(mb_base + (0 * 2 + 1) * 8, 1024 * GCH);
        mbar_arrive_expect(mb_base + (1 * 2 + 1) * 8, 1024 * GCH);
    }
    __syncthreads();
    cl_sync();   // barriers + zeroed buffers visible cluster-wide

    // ---- matvec mapping: 2 rows x one k-quarter ----
    const int q  = warp & 3;            // k-quarter 0..3
    const int g  = warp >> 2;           // row-group 0..2
    const int r0 = g * 32 + lane;       // 0..95
    const int r1 = r0 + 96;             // 96..191
    const int Rg0 = (r0 >> 6) * 256 + (int)rank * 64 + (r0 & 63);
    const int Rg1 = (r1 >> 6) * 256 + (int)rank * 64 + (r1 & 63);

    // 2 x 64 weights in registers (64 packed f32x2 total)
    unsigned long long wA[32], wB[32];
    {
        const ulonglong2* w0 = (const ulonglong2*)(Whh + (size_t)Rg0 * H_ + q * 64);
        const ulonglong2* w1 = (const ulonglong2*)(Whh + (size_t)Rg1 * H_ + q * 64);
        #pragma unroll
        for (int i = 0; i < 16; ++i) {
            ulonglong2 t0 = w0[i];
            wA[2 * i] = t0.x; wA[2 * i + 1] = t0.y;
            ulonglong2 t1 = w1[i];
            wB[2 * i] = t1.x; wB[2 * i + 1] = t1.y;
        }
    }

    // ---- gate mapping: one (chain, coord) per thread ----
    const int gc = tid >> 6;            // chain 0..5 (group = gc/3)
    const int gj = tid & 63;            // coord 0..63
    const int ggrp = (gc >= GCH) ? 1 : 0;
    const int gbase = (lcl * CHAINS + gc) * CHUNK;
    const int goff  = (int)rank * 64 + gj;
    const float* gpt;
    {
        int p0 = gbase - WARMUP; if (p0 < 0) p0 = 0;
        gpt = gi + (size_t)p0 * G3_ + goff;
    }

    // peer addresses
    uint32_t peer_hb[4], peer_mb[4];
    {
        uint32_t my_hb = smem_u32(&hbuf[0][0][0]);
        #pragma unroll
        for (int r = 0; r < 4; ++r) {
            peer_hb[r] = mapa_u32(my_hb, r);
            peer_mb[r] = mapa_u32(mb_base, r);
        }
    }

    uint32_t mph[2][2] = {{0u, 0u}, {0u, 0u}};

    for (int s = 0; s < STEPS; ++s) {
        const int ph = s & 1;

        // gi loads for THIS step (issued before the waits: hidden)
        float gv0 = __ldg(gpt);
        float gv1 = __ldg(gpt + 256);
        float gv2 = __ldg(gpt + 512);
        if (gbase + s + 1 > WARMUP) gpt += G3_;

        // ================= two pipelined groups =================
        #pragma unroll
        for (int grp = 0; grp < 2; ++grp) {
            const uint32_t mb = mb_base + (uint32_t)(grp * 2 + ph) * 8u;

            // wait for this group's h(s)
            if (s > 0) {
                mbar_wait_parity(mb, mph[grp][ph] & 1u);
                mph[grp][ph]++;
            }
            // arm for step (s+1)'s stores — after the wait (proven ordering)
            if (tid == 0 && s + 1 < STEPS)
                mbar_arrive_expect(mb, 1024 * GCH);

            // matvec for this group's 3 chains
            #pragma unroll
            for (int ci = 0; ci < GCH; ++ci) {
                const int c = grp * GCH + ci;
                const ulonglong2* h2 =
                    (const ulonglong2*)(&hbuf[ph][c][0]) + q * 16;
                unsigned long long a = 0ull, b = 0ull;
                #pragma unroll
                for (int i = 0; i < 16; ++i) {
                    ulonglong2 hv = h2[i];        // 1 LDS.128 -> 4 FFMA2
                    a = ffma2(wA[2 * i],     hv.x, a);
                    a = ffma2(wA[2 * i + 1], hv.y, a);
                    b = ffma2(wB[2 * i],     hv.x, b);
                    b = ffma2(wB[2 * i + 1], hv.y, b);
                }
                sGHp[c][q][r0] = f2lo(a) + f2hi(a);
                sGHp[c][q][r1] = f2lo(b) + f2hi(b);
            }
            __syncthreads();   // group partials visible; arm before stores

            // gates for this group: threads whose chain is in the group
            if (ggrp == grp) {
                const int p = gbase + s - WARMUP;

                float ghr = sGHp[gc][0][gj]       + sGHp[gc][1][gj]
                          + sGHp[gc][2][gj]       + sGHp[gc][3][gj]       + sBH[gj];
                float ghz = sGHp[gc][0][64 + gj]  + sGHp[gc][1][64 + gj]
                          + sGHp[gc][2][64 + gj]  + sGHp[gc][3][64 + gj]  + sBH[64 + gj];
                float ghn = sGHp[gc][0][128 + gj] + sGHp[gc][1][128 + gj]
                          + sGHp[gc][2][128 + gj] + sGHp[gc][3][128 + gj] + sBH[128 + gj];
                float r_ = sig_(gv0 + ghr);
                float z_ = sig_(gv1 + ghz);
                float n_ = th_ (gv2 + r_ * ghn);
                float hold = hbuf[ph][gc][goff];
                float hn = (1.0f - z_) * n_ + z_ * hold;
                if (p < 0) hn = 0.0f;   // pre-sequence region of chain 0

                if (s + 1 < STEPS) {
                    uint32_t boff = (uint32_t)(((ph ^ 1) * CHAINS + gc) * 256 + goff) * 4u;
                    uint32_t moff = (uint32_t)(grp * 2 + (ph ^ 1)) * 8u;
                    #pragma unroll
                    for (int r = 0; r < 4; ++r)
                        st_async_f32(peer_hb[r] + boff, hn, peer_mb[r] + moff);
                }

                if (s >= WARMUP) {
                    if (enc) {
                        if ((p & 127) == 127) {
                            int t_out = p >> 7;
                            out[(size_t)t_out * H_ + goff] = hn;
                        }
                    } else {
                        int b = p & 127, t = p >> 7;
                        out[(size_t)(T_IN_ * H_) +
                            ((size_t)b * T_OUT_ + t) * H_ + goff] = hn;
                    }
                }
            }
            // sGHp WAR across steps: this group's next-step matvec writes
            // are separated from these reads by the other group's
            // syncthreads (this step) + this group's wait (next step).
        }
    }

    cl_sync();   // drain async traffic before cluster teardown
}

// ============================================================
// launch
// ============================================================
extern "C" void kernel_launch(void* const* d_in, const int* in_sizes, int n_in,
                              void* d_out, int out_size)
{
    const float* x     = (const float*)d_in[0];
    const float* Wih_e = (const float*)d_in[1];
    const float* Whh_e = (const float*)d_in[2];
    const float* bih_e = (const float*)d_in[3];
    const float* bhh_e = (const float*)d_in[4];
    const float* Wih_d = (const float*)d_in[5];
    const float* Whh_d = (const float*)d_in[6];
    const float* bih_d = (const float*)d_in[7];
    const float* bhh_d = (const float*)d_in[8];
    float* out = (float*)d_out;

    dim3 ggrid(ENC_LEN / 64 + DEC_LEN / 64, G3_ / 64);  // (540, 12)
    gi_gemm<<<ggrid, 256>>>(x, Wih_e, bih_e, Wih_d, bih_d);

    gru_scan<<<(NCL_ENC + NCL_DEC) * 4, NTHREADS>>>(
        Whh_e, bhh_e, Whh_d, bhh_d, out);
}

// round 15
// speedup vs baseline: 1.5856x; 1.1003x over previous
#include <cuda_runtime.h>
#include <cstdint>

// ---------------- problem constants ----------------
#define B_      128
#define T_IN_   240
#define T_OUT_  30
#define D_      128
#define H_      256
#define G3_     768

#define ENC_LEN 30720   // T_IN * B
#define DEC_LEN 3840    // T_OUT * B

// segmentation: 6 chains per 4-CTA cluster, 2 pipelined groups of 3
#define CHAINS   6
#define GCH      3       // chains per group
#define CHUNK    160     // 192 enc chains * 160 = 30720 ; 24 dec chains * 160 = 3840
#define WARMUP   64
#define STEPS    (CHUNK + WARMUP)   // 224
#define NCL_ENC  32
#define NCL_DEC  4

#define NTHREADS 384     // 12 warps; every thread is one gate (c,j)

// ---------------- device scratch ----------------
__device__ float g_gi_enc[(size_t)ENC_LEN * G3_];   // ~94 MB
__device__ float g_gi_dec[(size_t)DEC_LEN * G3_];   // ~12 MB

// ---------------- helpers ----------------
__device__ __forceinline__ uint32_t smem_u32(const void* p) {
    return (uint32_t)__cvta_generic_to_shared(p);
}
__device__ __forceinline__ uint32_t mapa_u32(uint32_t addr, uint32_t rank) {
    uint32_t d;
    asm("mapa.shared::cluster.u32 %0, %1, %2;" : "=r"(d) : "r"(addr), "r"(rank));
    return d;
}
__device__ __forceinline__ void cl_sync() {
    asm volatile("barrier.cluster.arrive.aligned;" ::: "memory");
    asm volatile("barrier.cluster.wait.aligned;"   ::: "memory");
}
__device__ __forceinline__ void mbar_init(uint32_t mbar, uint32_t count) {
    asm volatile("mbarrier.init.shared.b64 [%0], %1;" :: "r"(mbar), "r"(count) : "memory");
}
__device__ __forceinline__ void mbar_arrive_expect(uint32_t mbar, uint32_t bytes) {
    asm volatile("mbarrier.arrive.expect_tx.shared::cta.b64 _, [%0], %1;"
                 :: "r"(mbar), "r"(bytes) : "memory");
}
__device__ __forceinline__ void mbar_wait_parity(uint32_t mbar, uint32_t parity) {
    uint32_t done;
    asm volatile(
        "{\n\t.reg .pred p;\n\t"
        "mbarrier.try_wait.parity.acquire.cta.shared::cta.b64 p, [%1], %2;\n\t"
        "selp.b32 %0, 1, 0, p;\n\t}"
        : "=r"(done) : "r"(mbar), "r"(parity) : "memory");
    if (!done) {
        asm volatile(
            "{\n\t.reg .pred P1;\n\t"
            "WAIT_LOOP_%=:\n\t"
            "mbarrier.try_wait.parity.acquire.cta.shared::cta.b64 P1, [%0], %1, 0x989680;\n\t"
            "@P1 bra.uni WAIT_DONE_%=;\n\t"
            "bra.uni WAIT_LOOP_%=;\n\t"
            "WAIT_DONE_%=:\n\t}"
            :: "r"(mbar), "r"(parity) : "memory");
    }
}
__device__ __forceinline__ void st_async_f32(uint32_t addr, float v, uint32_t mbar) {
    asm volatile(
        "st.async.weak.shared::cluster.mbarrier::complete_tx::bytes.f32 [%0], %1, [%2];"
        :: "r"(addr), "f"(v), "r"(mbar) : "memory");
}
__device__ __forceinline__ unsigned long long ffma2(unsigned long long a,
                                                    unsigned long long b,
                                                    unsigned long long c) {
    unsigned long long r;
    asm("fma.rn.f32x2 %0, %1, %2, %3;" : "=l"(r) : "l"(a), "l"(b), "l"(c));
    return r;
}
__device__ __forceinline__ unsigned long long pack2(float lo, float hi) {
    unsigned long long r;
    asm("mov.b64 %0, {%1, %2};" : "=l"(r) : "f"(lo), "f"(hi));
    return r;
}
__device__ __forceinline__ float f2lo(unsigned long long v) {
    return __uint_as_float((unsigned)(v & 0xffffffffull));
}
__device__ __forceinline__ float f2hi(unsigned long long v) {
    return __uint_as_float((unsigned)(v >> 32));
}
__device__ __forceinline__ float tanh_ap(float x) {
    float y;
    asm("tanh.approx.f32 %0, %1;" : "=f"(y) : "f"(x));
    return y;
}
__device__ __forceinline__ float sig_(float x) { return 0.5f * tanh_ap(0.5f * x) + 0.5f; }
__device__ __forceinline__ float th_(float x)  { return tanh_ap(x); }

// ============================================================
// Phase 1: GI = X @ Wih^T + bih — packed f32x2 micro-kernel.
// 4x4 per-thread tile computed as 2 pos-pairs x 4 gates:
//   8 FFMA2 + 4 ALU packs per k (vs 16 scalar FFMA).
// ============================================================
__global__ __launch_bounds__(256)
void gi_gemm(const float* __restrict__ x,
             const float* __restrict__ Wih_e, const float* __restrict__ bih_e,
             const float* __restrict__ Wih_d, const float* __restrict__ bih_d)
{
    __shared__ float Xs[64][68];   // [k][pos]
    __shared__ float Ws[64][68];   // [k][gate]

    const int tileP = blockIdx.x;
    const bool enc = (tileP < (ENC_LEN / 64));
    const float* __restrict__ Wih = enc ? Wih_e : Wih_d;
    const float* __restrict__ bih = enc ? bih_e : bih_d;
    float* __restrict__ gout = enc ? g_gi_enc : g_gi_dec;
    const int p0 = (enc ? tileP : (tileP - ENC_LEN / 64)) * 64;
    const int g0 = blockIdx.y * 64;
    const int tid = threadIdx.x;
    const int tstride = enc ? 1 : 8;

    const int tx = tid & 15;
    const int ty = tid >> 4;
    unsigned long long acc2[2][4] = {};   // [pos-pair][gate], packed f32x2

    for (int kc = 0; kc < 2; ++kc) {
        #pragma unroll
        for (int i = tid; i < 64 * 64; i += 256) {
            int pos = i >> 6, k = i & 63;
            int p = p0 + pos;
            int b = p & 127, t = (p >> 7) * tstride;
            Xs[k][pos] = x[((size_t)b * T_IN_ + t) * D_ + kc * 64 + k];
        }
        #pragma unroll
        for (int i = tid; i < 64 * 64; i += 256) {
            int g = i >> 6, k = i & 63;
            Ws[k][g] = Wih[(size_t)(g0 + g) * D_ + kc * 64 + k];
        }
        __syncthreads();

        #pragma unroll 8
        for (int k = 0; k < 64; ++k) {
            float4 a = *(const float4*)&Xs[k][ty * 4];
            float4 b = *(const float4*)&Ws[k][tx * 4];
            unsigned long long A01 = pack2(a.x, a.y);
            unsigned long long A23 = pack2(a.z, a.w);
            float bv[4] = {b.x, b.y, b.z, b.w};
            #pragma unroll
            for (int j = 0; j < 4; ++j) {
                unsigned long long Bjj = pack2(bv[j], bv[j]);
                acc2[0][j] = ffma2(A01, Bjj, acc2[0][j]);
                acc2[1][j] = ffma2(A23, Bjj, acc2[1][j]);
            }
        }
        __syncthreads();
    }

    float bz[4];
    #pragma unroll
    for (int j = 0; j < 4; ++j) bz[j] = bih[g0 + tx * 4 + j];

    #pragma unroll
    for (int i = 0; i < 4; ++i) {
        int p = p0 + ty * 4 + i;
        const int pair = i >> 1;
        const bool hi = (i & 1);
        float4 o;
        o.x = (hi ? f2hi(acc2[pair][0]) : f2lo(acc2[pair][0])) + bz[0];
        o.y = (hi ? f2hi(acc2[pair][1]) : f2lo(acc2[pair][1])) + bz[1];
        o.z = (hi ? f2hi(acc2[pair][2]) : f2lo(acc2[pair][2])) + bz[2];
        o.w = (hi ? f2hi(acc2[pair][3]) : f2lo(acc2[pair][3])) + bz[3];
        *(float4*)&gout[(size_t)p * G3_ + g0 + tx * 4] = o;
    }
}

// ============================================================
// Phase 2: segmented GRU scan — 6 chains in 2 pipelined groups.
// (identical to R14 proven kernel; only WARMUP changed 96->64)
// ============================================================
__global__ __launch_bounds__(NTHREADS, 1) __cluster_dims__(4, 1, 1)
void gru_scan(const float* __restrict__ Whh_e, const float* __restrict__ bhh_e,
              const float* __restrict__ Whh_d, const float* __restrict__ bhh_d,
              float* __restrict__ out)
{
    __shared__ __align__(16) float hbuf[2][CHAINS][256];   // [parity][chain][H]
    __shared__ float sGHp[CHAINS][4][192];                 // [chain][quarter][row]
    __shared__ float sBH[192];
    __shared__ __align__(8) unsigned long long mbars[2][2]; // [group][parity]

    const int tid  = threadIdx.x;
    const int warp = tid >> 5;
    const int lane = tid & 31;
    uint32_t rank;
    asm("mov.u32 %0, %%cluster_ctarank;" : "=r"(rank));

    const int cl   = blockIdx.x >> 2;
    const bool enc = cl < NCL_ENC;
    const int lcl  = enc ? cl : cl - NCL_ENC;
    const float* __restrict__ Whh = enc ? Whh_e : Whh_d;
    const float* __restrict__ bhh = enc ? bhh_e : bhh_d;
    const float* __restrict__ gi  = enc ? g_gi_enc : g_gi_dec;

    const uint32_t mb_base = smem_u32(&mbars[0][0]);
    // mbar addr: mb_base + (group*2 + parity)*8

    // ---- shared init ----
    for (int i = tid; i < 2 * CHAINS * 256; i += NTHREADS)
        ((float*)hbuf)[i] = 0.0f;
    if (tid < 192) {
        int g = tid >> 6, j = tid & 63;
        sBH[tid] = bhh[g * 256 + (int)rank * 64 + j];
    }
    if (tid == 0) {
        #pragma unroll
        for (int i = 0; i < 4; ++i) mbar_init(mb_base + i * 8, 1);
        // pre-arm parity-1 barriers of both groups (step-0 stores land there)
        mbar_arrive_expect(mb_base + (0 * 2 + 1) * 8, 1024 * GCH);
        mbar_arrive_expect(mb_base + (1 * 2 + 1) * 8, 1024 * GCH);
    }
    __syncthreads();
    cl_sync();   // barriers + zeroed buffers visible cluster-wide

    // ---- matvec mapping: 2 rows x one k-quarter ----
    const int q  = warp & 3;            // k-quarter 0..3
    const int g  = warp >> 2;           // row-group 0..2
    const int r0 = g * 32 + lane;       // 0..95
    const int r1 = r0 + 96;             // 96..191
    const int Rg0 = (r0 >> 6) * 256 + (int)rank * 64 + (r0 & 63);
    const int Rg1 = (r1 >> 6) * 256 + (int)rank * 64 + (r1 & 63);

    // 2 x 64 weights in registers (64 packed f32x2 total)
    unsigned long long wA[32], wB[32];
    {
        const ulonglong2* w0 = (const ulonglong2*)(Whh + (size_t)Rg0 * H_ + q * 64);
        const ulonglong2* w1 = (const ulonglong2*)(Whh + (size_t)Rg1 * H_ + q * 64);
        #pragma unroll
        for (int i = 0; i < 16; ++i) {
            ulonglong2 t0 = w0[i];
            wA[2 * i] = t0.x; wA[2 * i + 1] = t0.y;
            ulonglong2 t1 = w1[i];
            wB[2 * i] = t1.x; wB[2 * i + 1] = t1.y;
        }
    }

    // ---- gate mapping: one (chain, coord) per thread ----
    const int gc = tid >> 6;            // chain 0..5 (group = gc/3)
    const int gj = tid & 63;            // coord 0..63
    const int ggrp = (gc >= GCH) ? 1 : 0;
    const int gbase = (lcl * CHAINS + gc) * CHUNK;
    const int goff  = (int)rank * 64 + gj;
    const float* gpt;
    {
        int p0 = gbase - WARMUP; if (p0 < 0) p0 = 0;
        gpt = gi + (size_t)p0 * G3_ + goff;
    }

    // peer addresses
    uint32_t peer_hb[4], peer_mb[4];
    {
        uint32_t my_hb = smem_u32(&hbuf[0][0][0]);
        #pragma unroll
        for (int r = 0; r < 4; ++r) {
            peer_hb[r] = mapa_u32(my_hb, r);
            peer_mb[r] = mapa_u32(mb_base, r);
        }
    }

    uint32_t mph[2][2] = {{0u, 0u}, {0u, 0u}};

    for (int s = 0; s < STEPS; ++s) {
        const int ph = s & 1;

        // gi loads for THIS step (issued before the waits: hidden)
        float gv0 = __ldg(gpt);
        float gv1 = __ldg(gpt + 256);
        float gv2 = __ldg(gpt + 512);
        if (gbase + s + 1 > WARMUP) gpt += G3_;

        // ================= two pipelined groups =================
        #pragma unroll
        for (int grp = 0; grp < 2; ++grp) {
            const uint32_t mb = mb_base + (uint32_t)(grp * 2 + ph) * 8u;

            // wait for this group's h(s)
            if (s > 0) {
                mbar_wait_parity(mb, mph[grp][ph] & 1u);
                mph[grp][ph]++;
            }
            // arm for step (s+1)'s stores — after the wait (proven ordering)
            if (tid == 0 && s + 1 < STEPS)
                mbar_arrive_expect(mb, 1024 * GCH);

            // matvec for this group's 3 chains
            #pragma unroll
            for (int ci = 0; ci < GCH; ++ci) {
                const int c = grp * GCH + ci;
                const ulonglong2* h2 =
                    (const ulonglong2*)(&hbuf[ph][c][0]) + q * 16;
                unsigned long long a = 0ull, b = 0ull;
                #pragma unroll
                for (int i = 0; i < 16; ++i) {
                    ulonglong2 hv = h2[i];        // 1 LDS.128 -> 4 FFMA2
                    a = ffma2(wA[2 * i],     hv.x, a);
                    a = ffma2(wA[2 * i + 1], hv.y, a);
                    b = ffma2(wB[2 * i],     hv.x, b);
                    b = ffma2(wB[2 * i + 1], hv.y, b);
                }
                sGHp[c][q][r0] = f2lo(a) + f2hi(a);
                sGHp[c][q][r1] = f2lo(b) + f2hi(b);
            }
            __syncthreads();   // group partials visible; arm before stores

            // gates for this group: threads whose chain is in the group
            if (ggrp == grp) {
                const int p = gbase + s - WARMUP;

                float ghr = sGHp[gc][0][gj]       + sGHp[gc][1][gj]
                          + sGHp[gc][2][gj]       + sGHp[gc][3][gj]       + sBH[gj];
                float ghz = sGHp[gc][0][64 + gj]  + sGHp[gc][1][64 + gj]
                          + sGHp[gc][2][64 + gj]  + sGHp[gc][3][64 + gj]  + sBH[64 + gj];
                float ghn = sGHp[gc][0][128 + gj] + sGHp[gc][1][128 + gj]
                          + sGHp[gc][2][128 + gj] + sGHp[gc][3][128 + gj] + sBH[128 + gj];
                float r_ = sig_(gv0 + ghr);
                float z_ = sig_(gv1 + ghz);
                float n_ = th_ (gv2 + r_ * ghn);
                float hold = hbuf[ph][gc][goff];
                float hn = (1.0f - z_) * n_ + z_ * hold;
                if (p < 0) hn = 0.0f;   // pre-sequence region of chain 0

                if (s + 1 < STEPS) {
                    uint32_t boff = (uint32_t)(((ph ^ 1) * CHAINS + gc) * 256 + goff) * 4u;
                    uint32_t moff = (uint32_t)(grp * 2 + (ph ^ 1)) * 8u;
                    #pragma unroll
                    for (int r = 0; r < 4; ++r)
                        st_async_f32(peer_hb[r] + boff, hn, peer_mb[r] + moff);
                }

                if (s >= WARMUP) {
                    if (enc) {
                        if ((p & 127) == 127) {
                            int t_out = p >> 7;
                            out[(size_t)t_out * H_ + goff] = hn;
                        }
                    } else {
                        int b = p & 127, t = p >> 7;
                        out[(size_t)(T_IN_ * H_) +
                            ((size_t)b * T_OUT_ + t) * H_ + goff] = hn;
                    }
                }
            }
            // sGHp WAR across steps: this group's next-step matvec writes
            // are separated from these reads by the other group's
            // syncthreads (this step) + this group's wait (next step).
        }
    }

    cl_sync();   // drain async traffic before cluster teardown
}

// ============================================================
// launch
// ============================================================
extern "C" void kernel_launch(void* const* d_in, const int* in_sizes, int n_in,
                              void* d_out, int out_size)
{
    const float* x     = (const float*)d_in[0];
    const float* Wih_e = (const float*)d_in[1];
    const float* Whh_e = (const float*)d_in[2];
    const float* bih_e = (const float*)d_in[3];
    const float* bhh_e = (const float*)d_in[4];
    const float* Wih_d = (const float*)d_in[5];
    const float* Whh_d = (const float*)d_in[6];
    const float* bih_d = (const float*)d_in[7];
    const float* bhh_d = (const float*)d_in[8];
    float* out = (float*)d_out;

    dim3 ggrid(ENC_LEN / 64 + DEC_LEN / 64, G3_ / 64);  // (540, 12)
    gi_gemm<<<ggrid, 256>>>(x, Wih_e, bih_e, Wih_d, bih_d);

    gru_scan<<<(NCL_ENC + NCL_DEC) * 4, NTHREADS>>>(
        Whh_e, bhh_e, Whh_d, bhh_d, out);
}